// round 14
// baseline (speedup 1.0000x reference)
#include <cuda_runtime.h>

#define NT 128
#define PI_F 3.14159265358979323846f

// ---------- packed f32x2 primitives ----------
struct P2 { union { float2 f; unsigned long long u; }; };

__device__ __forceinline__ P2 mk2(float a, float b) { P2 p; p.f.x = a; p.f.y = b; return p; }
__device__ __forceinline__ P2 dup2(float a) { return mk2(a, a); }

__device__ __forceinline__ P2 fma2(P2 a, P2 b, P2 c) {
    P2 d;
    asm("fma.rn.f32x2 %0, %1, %2, %3;" : "=l"(d.u) : "l"(a.u), "l"(b.u), "l"(c.u));
    return d;
}
__device__ __forceinline__ P2 mul2(P2 a, P2 b) {
    P2 d;
    asm("mul.rn.f32x2 %0, %1, %2;" : "=l"(d.u) : "l"(a.u), "l"(b.u));
    return d;
}
__device__ __forceinline__ P2 relu2(P2 a) {
    P2 d; d.f.x = fmaxf(a.f.x, 0.f); d.f.y = fmaxf(a.f.y, 0.f); return d;
}

// Bloch-sphere / Pauli-string collapsed quantum encoder for one lane-packed row pair.
__device__ __forceinline__ void compute_zv(const float xsA[8], const float xsB[8],
                                           const float2* __restrict__ sK, P2 zv[4])
{
    P2 X[4], Y[4], Z[4];
#pragma unroll
    for (int i = 0; i < 4; i++) {
        float saA, caA, sbA, cbA, saB, caB, sbB, cbB;
        __sincosf(xsA[i]     * PI_F, &saA, &caA);
        __sincosf(xsA[i + 4] * PI_F, &sbA, &cbA);
        __sincosf(xsB[i]     * PI_F, &saB, &caB);
        __sincosf(xsB[i + 4] * PI_F, &sbB, &cbB);
        P2 sa = mk2(saA, saB), sb = mk2(sbA, sbB), cb = mk2(cbA, cbB);
        X[i] = mul2(sa, cb);
        Y[i] = mul2(sa, sb);
        Z[i] = mk2(caA, caB);
    }

    P2 A  = mul2(X[0], X[1]);
    P2 B  = mul2(Y[0], Y[1]);
    P2 F  = mul2(X[1], X[2]);
    P2 H  = mul2(X[0], X[2]);
    P2 D  = mul2(X[2], X[3]);
    P2 E  = mul2(Y[2], Y[3]);
    P2 G  = mul2(Y[1], Y[2]);
    P2 ZF = mul2(Z[0], F);
    P2 Z0Z2 = mul2(Z[0], Z[2]);
    P2 YZ   = mul2(Y[0], Z[1]);
    P2 YZY  = mul2(YZ, Y[2]);

#define KLD(n) ({ P2 _k; _k.f = sK[n]; _k; })

    P2 z0 = mul2(KLD(0), Z[0]);
    z0 = fma2(KLD(1), A, z0);

    P2 z1 = mul2(KLD(2), Z[1]);
    z1 = fma2(KLD(3), ZF, z1);
    z1 = fma2(KLD(4), B, z1);
    z1 = fma2(KLD(5), H, z1);

    P2 Z1D   = mul2(Z[1], D);
    P2 X1X3  = mul2(X[1], X[3]);
    P2 ZX1X3 = mul2(Z[0], X1X3);
    P2 AZ2   = mul2(A, Z[2]);
    P2 BD    = mul2(B, D);
    P2 X0X3  = mul2(X[0], X[3]);
    P2 z2 = mul2(KLD(6), Z0Z2);
    z2 = fma2(KLD(7),  Z1D,   z2);
    z2 = fma2(KLD(8),  G,     z2);
    z2 = fma2(KLD(9),  ZX1X3, z2);
    z2 = fma2(KLD(10), AZ2,   z2);
    z2 = fma2(KLD(11), BD,    z2);
    z2 = fma2(KLD(12), YZY,   z2);
    z2 = fma2(KLD(13), X0X3,  z2);

    P2 Z1Z3 = mul2(Z[1], Z[3]);
    P2 BZ3  = mul2(B, Z[3]);
    P2 ZF3  = mul2(ZF, Z[3]);
    P2 Z0E  = mul2(Z[0], E);
    P2 ZZX  = mul2(Z0Z2, X[3]);
    P2 HZ3  = mul2(H, Z[3]);
    P2 AE   = mul2(A, E);
    P2 AZX  = mul2(AZ2, X[3]);
    P2 Y1Z2 = mul2(Y[1], Z[2]);
    P2 YZ2Y3 = mul2(Y1Z2, Y[3]);
    P2 GX3  = mul2(G, X[3]);
    P2 Z1X2 = mul2(Z[1], X[2]);
    P2 YZZ  = mul2(YZ, Z[2]);
    P2 YZZY = mul2(YZZ, Y[3]);
    P2 YZYX = mul2(YZY, X[3]);
    P2 BX2  = mul2(B, X[2]);
    P2 Z0X1 = mul2(Z[0], X[1]);
    P2 z3 = mul2(KLD(14), Z1Z3);
    z3 = fma2(KLD(15), BZ3,   z3);
    z3 = fma2(KLD(16), ZF3,   z3);
    z3 = fma2(KLD(17), Z0E,   z3);
    z3 = fma2(KLD(18), ZZX,   z3);
    z3 = fma2(KLD(19), HZ3,   z3);
    z3 = fma2(KLD(20), AE,    z3);
    z3 = fma2(KLD(21), AZX,   z3);
    z3 = fma2(KLD(22), YZ2Y3, z3);
    z3 = fma2(KLD(23), GX3,   z3);
    z3 = fma2(KLD(24), Z1X2,  z3);
    z3 = fma2(KLD(25), YZZY,  z3);
    z3 = fma2(KLD(26), YZYX,  z3);
    z3 = fma2(KLD(27), BX2,   z3);
    z3 = fma2(KLD(28), Z0X1,  z3);
    z3 = fma2(KLD(29), X[0],  z3);

    zv[0] = z0; zv[1] = z1; zv[2] = z2; zv[3] = z3;
}

__global__ void __launch_bounds__(NT, 6)
qae14_kernel(const float* __restrict__ x,
             const float* __restrict__ qw,
             const float* __restrict__ W1, const float* __restrict__ b1,
             const float* __restrict__ W2, const float* __restrict__ b2,
             const float* __restrict__ W3, const float* __restrict__ b3,
             float* __restrict__ out, int nrows)
{
    // sW1: neuron-pair interleaved (pairs of L1 outputs).
    // sW2: PLAIN row-major [32][16] (L2 uses packed dot-products over h1 pairs).
    // sW3: neuron-pair interleaved [8 pairs][32 k].
    __shared__ __align__(16) float2 sW1[32];
    __shared__ __align__(16) float  sW2[512];
    __shared__ __align__(16) float2 sW3[256];
    __shared__ __align__(16) float2 sb1[8];
    __shared__ __align__(16) float  sb2[32];
    __shared__ __align__(16) float2 sb3[8];
    __shared__ __align__(8)  float2 sK[30];

    const int tid = threadIdx.x;
    for (int i = tid; i < 32; i += NT) {
        int p = i >> 2, k = i & 3;
        sW1[i] = make_float2(W1[(2 * p) * 4 + k], W1[(2 * p + 1) * 4 + k]);
    }
    for (int i = tid; i < 512; i += NT)
        sW2[i] = W2[i];   // plain row-major
    for (int i = tid; i < 256; i += NT) {
        int p3 = i >> 5, k3 = i & 31;   // 8 pairs x 32 k
        sW3[i] = make_float2(W3[(2 * p3) * 32 + k3], W3[(2 * p3 + 1) * 32 + k3]);
    }
    if (tid < 8)  sb1[tid] = make_float2(b1[2 * tid], b1[2 * tid + 1]);
    if (tid < 32) sb2[tid] = b2[tid];
    if (tid < 8)  sb3[tid] = make_float2(b3[2 * tid], b3[2 * tid + 1]);
    if (tid == 0) {
        float c[4], s[4];
#pragma unroll
        for (int i = 0; i < 4; i++) __sincosf(qw[2 * i], &s[i], &c[i]);
        float kv[30];
        kv[0]  =  c[0];                    kv[1]  = -s[0];
        kv[2]  =  c[0] * c[1];             kv[3]  = -c[0] * s[1];
        kv[4]  =  s[0] * c[1];             kv[5]  =  s[0] * s[1];
        kv[6]  =  c[0] * c[1] * c[2];      kv[7]  = -c[0] * c[1] * s[2];
        kv[8]  =  c[0] * s[1] * c[2];      kv[9]  =  c[0] * s[1] * s[2];
        kv[10] = -s[0] * c[1] * c[2];      kv[11] = -s[0] * c[1] * s[2];
        kv[12] = -s[0] * s[1] * c[2];      kv[13] = -s[0] * s[1] * s[2];
        kv[14] =  c[0] * c[1] * c[2] * c[3];
        kv[15] =  s[0] * c[1] * c[2] * c[3];
        kv[16] = -c[0] * s[1] * c[2] * c[3];
        kv[17] =  c[0] * c[1] * s[2] * c[3];
        kv[18] = -c[0] * c[1] * c[2] * s[3];
        kv[19] =  s[0] * s[1] * c[2] * c[3];
        kv[20] = -s[0] * c[1] * s[2] * c[3];
        kv[21] =  s[0] * c[1] * c[2] * s[3];
        kv[22] = -c[0] * s[1] * s[2] * c[3];
        kv[23] = -c[0] * s[1] * c[2] * s[3];
        kv[24] =  c[0] * c[1] * s[2] * s[3];
        kv[25] =  s[0] * s[1] * s[2] * c[3];
        kv[26] =  s[0] * s[1] * c[2] * s[3];
        kv[27] =  s[0] * c[1] * s[2] * s[3];
        kv[28] = -c[0] * s[1] * s[2] * s[3];
        kv[29] =  s[0] * s[1] * s[2] * s[3];
#pragma unroll
        for (int i = 0; i < 30; i++) sK[i] = make_float2(kv[i], kv[i]);
    }
    __syncthreads();

    const int r0 = blockIdx.x * (NT * 2) + tid;
    const int r1 = r0 + NT;
    if (r0 >= nrows) return;
    const bool has1 = (r1 < nrows);
    const int r1c = has1 ? r1 : r0;

    // ---- load features ----
    const float4* xp0 = reinterpret_cast<const float4*>(x + (size_t)r0 * 16);
    const float4* xp1 = reinterpret_cast<const float4*>(x + (size_t)r1c * 16);
    float4 a0 = xp0[0], a1 = xp0[1];
    float4 c0 = xp1[0], c1 = xp1[1];
    float xsA[8] = {a0.x, a0.y, a0.z, a0.w, a1.x, a1.y, a1.z, a1.w};
    float xsB[8] = {c0.x, c0.y, c0.z, c0.w, c1.x, c1.y, c1.z, c1.w};

    // ---- quantum encoder (lane-packed row pair) ----
    P2 zv[4];
    compute_zv(xsA, xsB, sK, zv);

    P2 zdA[4], zdB[4];
#pragma unroll
    for (int k = 0; k < 4; k++) { zdA[k] = dup2(zv[k].f.x); zdB[k] = dup2(zv[k].f.y); }

    // ---- Layer 1: 4 -> 16 ; h1 stored as neuron pairs (h1[2p], h1[2p+1]) ----
    P2 h1A[8], h1B[8];
#pragma unroll
    for (int pp = 0; pp < 8; pp++) {
        const float4* wp = reinterpret_cast<const float4*>(sW1 + pp * 4);
        float4 w0 = wp[0], w1 = wp[1];
        P2 wk0 = mk2(w0.x, w0.y), wk1 = mk2(w0.z, w0.w);
        P2 wk2 = mk2(w1.x, w1.y), wk3 = mk2(w1.z, w1.w);
        P2 accA; accA.f = sb1[pp];
        P2 accB = accA;
        accA = fma2(wk0, zdA[0], accA); accB = fma2(wk0, zdB[0], accB);
        accA = fma2(wk1, zdA[1], accA); accB = fma2(wk1, zdB[1], accB);
        accA = fma2(wk2, zdA[2], accA); accB = fma2(wk2, zdB[2], accB);
        accA = fma2(wk3, zdA[3], accA); accB = fma2(wk3, zdB[3], accB);
        h1A[pp] = relu2(accA); h1B[pp] = relu2(accB);
    }

    // ---- Fused Layers 2+3: h2 never materializes ----
    P2 oA[8], oB[8];
#pragma unroll
    for (int qq = 0; qq < 8; qq++) { oA[qq].f = sb3[qq]; oB[qq] = oA[qq]; }

#pragma unroll
    for (int ch = 0; ch < 16; ch++) {
        // L2: h2 neurons 2ch, 2ch+1 via packed dot products (bias seeds lane x)
        const float4* w2r0 = reinterpret_cast<const float4*>(sW2 + (2 * ch) * 16);
        const float4* w2r1 = reinterpret_cast<const float4*>(sW2 + (2 * ch + 1) * 16);
        P2 accA0 = mk2(sb2[2 * ch], 0.f);
        P2 accA1 = mk2(sb2[2 * ch + 1], 0.f);
        P2 accB0 = accA0, accB1 = accA1;
#pragma unroll
        for (int j4 = 0; j4 < 4; j4++) {
            float4 w0 = w2r0[j4];
            float4 w1 = w2r1[j4];
            P2 w0a = mk2(w0.x, w0.y), w0b = mk2(w0.z, w0.w);
            P2 w1a = mk2(w1.x, w1.y), w1b = mk2(w1.z, w1.w);
            P2 hA0 = h1A[2 * j4], hA1 = h1A[2 * j4 + 1];
            P2 hB0 = h1B[2 * j4], hB1 = h1B[2 * j4 + 1];
            accA0 = fma2(w0a, hA0, accA0); accA0 = fma2(w0b, hA1, accA0);
            accA1 = fma2(w1a, hA0, accA1); accA1 = fma2(w1b, hA1, accA1);
            accB0 = fma2(w0a, hB0, accB0); accB0 = fma2(w0b, hB1, accB0);
            accB1 = fma2(w1a, hB0, accB1); accB1 = fma2(w1b, hB1, accB1);
        }
        float nA0 = fmaxf(accA0.f.x + accA0.f.y, 0.f);
        float nA1 = fmaxf(accA1.f.x + accA1.f.y, 0.f);
        float nB0 = fmaxf(accB0.f.x + accB0.f.y, 0.f);
        float nB1 = fmaxf(accB1.f.x + accB1.f.y, 0.f);
        P2 hdA0 = dup2(nA0), hdA1 = dup2(nA1);
        P2 hdB0 = dup2(nB0), hdB1 = dup2(nB1);

        // L3 scatter: contribution of h2[2ch], h2[2ch+1] into all 16 outputs
#pragma unroll
        for (int qq = 0; qq < 8; qq++) {
            float4 w = *reinterpret_cast<const float4*>(sW3 + qq * 32 + ch * 2);
            P2 wa = mk2(w.x, w.y), wb = mk2(w.z, w.w);
            oA[qq] = fma2(wa, hdA0, oA[qq]);
            oB[qq] = fma2(wa, hdB0, oB[qq]);
            oA[qq] = fma2(wb, hdA1, oA[qq]);
            oB[qq] = fma2(wb, hdB1, oB[qq]);
        }
    }

    // ---- stores: oX[q] = (neuron 2q, neuron 2q+1) ----
    float4* op0 = reinterpret_cast<float4*>(out + (size_t)r0 * 16);
#pragma unroll
    for (int q = 0; q < 4; q++)
        op0[q] = make_float4(oA[2 * q].f.x, oA[2 * q].f.y, oA[2 * q + 1].f.x, oA[2 * q + 1].f.y);
    if (has1) {
        float4* op1 = reinterpret_cast<float4*>(out + (size_t)r1 * 16);
#pragma unroll
        for (int q = 0; q < 4; q++)
            op1[q] = make_float4(oB[2 * q].f.x, oB[2 * q].f.y, oB[2 * q + 1].f.x, oB[2 * q + 1].f.y);
    }
}

extern "C" void kernel_launch(void* const* d_in, const int* in_sizes, int n_in,
                              void* d_out, int out_size) {
    const float* x  = (const float*)d_in[0];
    const float* qw = (const float*)d_in[1];
    const float* W1 = (const float*)d_in[2];
    const float* b1 = (const float*)d_in[3];
    const float* W2 = (const float*)d_in[4];
    const float* b2 = (const float*)d_in[5];
    const float* W3 = (const float*)d_in[6];
    const float* b3 = (const float*)d_in[7];
    float* out = (float*)d_out;

    int nrows = in_sizes[0] / 16;
    int grid = (nrows + NT * 2 - 1) / (NT * 2);
    qae14_kernel<<<grid, NT>>>(x, qw, W1, b1, W2, b2, W3, b3, out, nrows);
}

// round 15
// speedup vs baseline: 1.3756x; 1.3756x over previous
#include <cuda_runtime.h>

#define NT 128
#define PI_F 3.14159265358979323846f

struct __align__(16) CData {
    float2 W1[32];    // neuron-pair interleaved: idx i -> p=i>>2,k=i&3 : (W1[2p][k], W1[2p+1][k])
    float  W2[512];   // plain row-major [32][16]
    float2 W3[256];   // pair-interleaved [8 pairs][32 k]
    float2 b1[8];
    float  b2[32];
    float2 b3[8];
    float2 K[30];     // Pauli coefficients, duplicated lanes
};

__constant__ CData cD;
__device__   CData gStage;

// ---------- packed f32x2 primitives ----------
struct P2 { union { float2 f; unsigned long long u; }; };

__device__ __forceinline__ P2 mk2(float a, float b) { P2 p; p.f.x = a; p.f.y = b; return p; }
__device__ __forceinline__ P2 dup2(float a) { return mk2(a, a); }

__device__ __forceinline__ P2 fma2(P2 a, P2 b, P2 c) {
    P2 d;
    asm("fma.rn.f32x2 %0, %1, %2, %3;" : "=l"(d.u) : "l"(a.u), "l"(b.u), "l"(c.u));
    return d;
}
__device__ __forceinline__ P2 mul2(P2 a, P2 b) {
    P2 d;
    asm("mul.rn.f32x2 %0, %1, %2;" : "=l"(d.u) : "l"(a.u), "l"(b.u));
    return d;
}
__device__ __forceinline__ P2 relu2(P2 a) {
    P2 d; d.f.x = fmaxf(a.f.x, 0.f); d.f.y = fmaxf(a.f.y, 0.f); return d;
}

// ---------- prep kernel: rearrange weights + compute coefficients into staging ----------
__global__ void qae_prep(const float* __restrict__ qw,
                         const float* __restrict__ W1, const float* __restrict__ b1,
                         const float* __restrict__ W2, const float* __restrict__ b2,
                         const float* __restrict__ W3, const float* __restrict__ b3)
{
    const int tid = threadIdx.x;
    for (int i = tid; i < 32; i += 256) {
        int p = i >> 2, k = i & 3;
        gStage.W1[i] = make_float2(W1[(2 * p) * 4 + k], W1[(2 * p + 1) * 4 + k]);
    }
    for (int i = tid; i < 512; i += 256)
        gStage.W2[i] = W2[i];
    for (int i = tid; i < 256; i += 256) {
        int p3 = i >> 5, k3 = i & 31;
        gStage.W3[i] = make_float2(W3[(2 * p3) * 32 + k3], W3[(2 * p3 + 1) * 32 + k3]);
    }
    if (tid < 8)  gStage.b1[tid] = make_float2(b1[2 * tid], b1[2 * tid + 1]);
    if (tid < 32) gStage.b2[tid] = b2[tid];
    if (tid < 8)  gStage.b3[tid] = make_float2(b3[2 * tid], b3[2 * tid + 1]);
    if (tid == 0) {
        float c[4], s[4];
#pragma unroll
        for (int i = 0; i < 4; i++) __sincosf(qw[2 * i], &s[i], &c[i]);
        float kv[30];
        kv[0]  =  c[0];                    kv[1]  = -s[0];
        kv[2]  =  c[0] * c[1];             kv[3]  = -c[0] * s[1];
        kv[4]  =  s[0] * c[1];             kv[5]  =  s[0] * s[1];
        kv[6]  =  c[0] * c[1] * c[2];      kv[7]  = -c[0] * c[1] * s[2];
        kv[8]  =  c[0] * s[1] * c[2];      kv[9]  =  c[0] * s[1] * s[2];
        kv[10] = -s[0] * c[1] * c[2];      kv[11] = -s[0] * c[1] * s[2];
        kv[12] = -s[0] * s[1] * c[2];      kv[13] = -s[0] * s[1] * s[2];
        kv[14] =  c[0] * c[1] * c[2] * c[3];
        kv[15] =  s[0] * c[1] * c[2] * c[3];
        kv[16] = -c[0] * s[1] * c[2] * c[3];
        kv[17] =  c[0] * c[1] * s[2] * c[3];
        kv[18] = -c[0] * c[1] * c[2] * s[3];
        kv[19] =  s[0] * s[1] * c[2] * c[3];
        kv[20] = -s[0] * c[1] * s[2] * c[3];
        kv[21] =  s[0] * c[1] * c[2] * s[3];
        kv[22] = -c[0] * s[1] * s[2] * c[3];
        kv[23] = -c[0] * s[1] * c[2] * s[3];
        kv[24] =  c[0] * c[1] * s[2] * s[3];
        kv[25] =  s[0] * s[1] * s[2] * c[3];
        kv[26] =  s[0] * s[1] * c[2] * s[3];
        kv[27] =  s[0] * c[1] * s[2] * s[3];
        kv[28] = -c[0] * s[1] * s[2] * s[3];
        kv[29] =  s[0] * s[1] * s[2] * s[3];
#pragma unroll
        for (int i = 0; i < 30; i++) gStage.K[i] = make_float2(kv[i], kv[i]);
    }
}

// Bloch-sphere / Pauli-string collapsed quantum encoder for one lane-packed row pair.
__device__ __forceinline__ void compute_zv(const float xsA[8], const float xsB[8], P2 zv[4])
{
    P2 X[4], Y[4], Z[4];
#pragma unroll
    for (int i = 0; i < 4; i++) {
        float saA, caA, sbA, cbA, saB, caB, sbB, cbB;
        __sincosf(xsA[i]     * PI_F, &saA, &caA);
        __sincosf(xsA[i + 4] * PI_F, &sbA, &cbA);
        __sincosf(xsB[i]     * PI_F, &saB, &caB);
        __sincosf(xsB[i + 4] * PI_F, &sbB, &cbB);
        P2 sa = mk2(saA, saB), sb = mk2(sbA, sbB), cb = mk2(cbA, cbB);
        X[i] = mul2(sa, cb);
        Y[i] = mul2(sa, sb);
        Z[i] = mk2(caA, caB);
    }

    P2 A  = mul2(X[0], X[1]);
    P2 B  = mul2(Y[0], Y[1]);
    P2 F  = mul2(X[1], X[2]);
    P2 H  = mul2(X[0], X[2]);
    P2 D  = mul2(X[2], X[3]);
    P2 E  = mul2(Y[2], Y[3]);
    P2 G  = mul2(Y[1], Y[2]);
    P2 ZF = mul2(Z[0], F);
    P2 Z0Z2 = mul2(Z[0], Z[2]);
    P2 YZ   = mul2(Y[0], Z[1]);
    P2 YZY  = mul2(YZ, Y[2]);

#define KLD(n) ({ P2 _k; _k.f = cD.K[n]; _k; })

    P2 z0 = mul2(KLD(0), Z[0]);
    z0 = fma2(KLD(1), A, z0);

    P2 z1 = mul2(KLD(2), Z[1]);
    z1 = fma2(KLD(3), ZF, z1);
    z1 = fma2(KLD(4), B, z1);
    z1 = fma2(KLD(5), H, z1);

    P2 Z1D   = mul2(Z[1], D);
    P2 X1X3  = mul2(X[1], X[3]);
    P2 ZX1X3 = mul2(Z[0], X1X3);
    P2 AZ2   = mul2(A, Z[2]);
    P2 BD    = mul2(B, D);
    P2 X0X3  = mul2(X[0], X[3]);
    P2 z2 = mul2(KLD(6), Z0Z2);
    z2 = fma2(KLD(7),  Z1D,   z2);
    z2 = fma2(KLD(8),  G,     z2);
    z2 = fma2(KLD(9),  ZX1X3, z2);
    z2 = fma2(KLD(10), AZ2,   z2);
    z2 = fma2(KLD(11), BD,    z2);
    z2 = fma2(KLD(12), YZY,   z2);
    z2 = fma2(KLD(13), X0X3,  z2);

    P2 Z1Z3 = mul2(Z[1], Z[3]);
    P2 BZ3  = mul2(B, Z[3]);
    P2 ZF3  = mul2(ZF, Z[3]);
    P2 Z0E  = mul2(Z[0], E);
    P2 ZZX  = mul2(Z0Z2, X[3]);
    P2 HZ3  = mul2(H, Z[3]);
    P2 AE   = mul2(A, E);
    P2 AZX  = mul2(AZ2, X[3]);
    P2 Y1Z2 = mul2(Y[1], Z[2]);
    P2 YZ2Y3 = mul2(Y1Z2, Y[3]);
    P2 GX3  = mul2(G, X[3]);
    P2 Z1X2 = mul2(Z[1], X[2]);
    P2 YZZ  = mul2(YZ, Z[2]);
    P2 YZZY = mul2(YZZ, Y[3]);
    P2 YZYX = mul2(YZY, X[3]);
    P2 BX2  = mul2(B, X[2]);
    P2 Z0X1 = mul2(Z[0], X[1]);
    P2 z3 = mul2(KLD(14), Z1Z3);
    z3 = fma2(KLD(15), BZ3,   z3);
    z3 = fma2(KLD(16), ZF3,   z3);
    z3 = fma2(KLD(17), Z0E,   z3);
    z3 = fma2(KLD(18), ZZX,   z3);
    z3 = fma2(KLD(19), HZ3,   z3);
    z3 = fma2(KLD(20), AE,    z3);
    z3 = fma2(KLD(21), AZX,   z3);
    z3 = fma2(KLD(22), YZ2Y3, z3);
    z3 = fma2(KLD(23), GX3,   z3);
    z3 = fma2(KLD(24), Z1X2,  z3);
    z3 = fma2(KLD(25), YZZY,  z3);
    z3 = fma2(KLD(26), YZYX,  z3);
    z3 = fma2(KLD(27), BX2,   z3);
    z3 = fma2(KLD(28), Z0X1,  z3);
    z3 = fma2(KLD(29), X[0],  z3);

    zv[0] = z0; zv[1] = z1; zv[2] = z2; zv[3] = z3;
}

__global__ void __launch_bounds__(NT)
qae15_kernel(const float* __restrict__ x, float* __restrict__ out, int nrows)
{
    const int tid = threadIdx.x;
    const int r0 = blockIdx.x * (NT * 2) + tid;
    const int r1 = r0 + NT;
    if (r0 >= nrows) return;
    const bool has1 = (r1 < nrows);
    const int r1c = has1 ? r1 : r0;

    // ---- load features ----
    const float4* xp0 = reinterpret_cast<const float4*>(x + (size_t)r0 * 16);
    const float4* xp1 = reinterpret_cast<const float4*>(x + (size_t)r1c * 16);
    float4 a0 = xp0[0], a1 = xp0[1];
    float4 c0 = xp1[0], c1 = xp1[1];
    float xsA[8] = {a0.x, a0.y, a0.z, a0.w, a1.x, a1.y, a1.z, a1.w};
    float xsB[8] = {c0.x, c0.y, c0.z, c0.w, c1.x, c1.y, c1.z, c1.w};

    // ---- quantum encoder (lane-packed row pair) ----
    P2 zv[4];
    compute_zv(xsA, xsB, zv);

    P2 zdA[4], zdB[4];
#pragma unroll
    for (int k = 0; k < 4; k++) { zdA[k] = dup2(zv[k].f.x); zdB[k] = dup2(zv[k].f.y); }

    // ---- Layer 1: 4 -> 16 ; h1 stored as neuron pairs (h1[2p], h1[2p+1]) ----
    P2 h1A[8], h1B[8];
#pragma unroll
    for (int pp = 0; pp < 8; pp++) {
        const float4* wp = reinterpret_cast<const float4*>(cD.W1 + pp * 4);
        float4 w0 = wp[0], w1 = wp[1];
        P2 wk0 = mk2(w0.x, w0.y), wk1 = mk2(w0.z, w0.w);
        P2 wk2 = mk2(w1.x, w1.y), wk3 = mk2(w1.z, w1.w);
        P2 accA; accA.f = cD.b1[pp];
        P2 accB = accA;
        accA = fma2(wk0, zdA[0], accA); accB = fma2(wk0, zdB[0], accB);
        accA = fma2(wk1, zdA[1], accA); accB = fma2(wk1, zdB[1], accB);
        accA = fma2(wk2, zdA[2], accA); accB = fma2(wk2, zdB[2], accB);
        accA = fma2(wk3, zdA[3], accA); accB = fma2(wk3, zdB[3], accB);
        h1A[pp] = relu2(accA); h1B[pp] = relu2(accB);
    }

    // ---- Fused Layers 2+3: h2 never materializes ----
    P2 oA[8], oB[8];
#pragma unroll
    for (int qq = 0; qq < 8; qq++) { oA[qq].f = cD.b3[qq]; oB[qq] = oA[qq]; }

#pragma unroll
    for (int ch = 0; ch < 16; ch++) {
        // L2: h2 neurons 2ch, 2ch+1 via packed dot products (bias seeds lane x)
        const float4* w2r0 = reinterpret_cast<const float4*>(cD.W2 + (2 * ch) * 16);
        const float4* w2r1 = reinterpret_cast<const float4*>(cD.W2 + (2 * ch + 1) * 16);
        P2 accA0 = mk2(cD.b2[2 * ch], 0.f);
        P2 accA1 = mk2(cD.b2[2 * ch + 1], 0.f);
        P2 accB0 = accA0, accB1 = accA1;
#pragma unroll
        for (int j4 = 0; j4 < 4; j4++) {
            float4 w0 = w2r0[j4];
            float4 w1 = w2r1[j4];
            P2 w0a = mk2(w0.x, w0.y), w0b = mk2(w0.z, w0.w);
            P2 w1a = mk2(w1.x, w1.y), w1b = mk2(w1.z, w1.w);
            P2 hA0 = h1A[2 * j4], hA1 = h1A[2 * j4 + 1];
            P2 hB0 = h1B[2 * j4], hB1 = h1B[2 * j4 + 1];
            accA0 = fma2(w0a, hA0, accA0); accA0 = fma2(w0b, hA1, accA0);
            accA1 = fma2(w1a, hA0, accA1); accA1 = fma2(w1b, hA1, accA1);
            accB0 = fma2(w0a, hB0, accB0); accB0 = fma2(w0b, hB1, accB0);
            accB1 = fma2(w1a, hB0, accB1); accB1 = fma2(w1b, hB1, accB1);
        }
        float nA0 = fmaxf(accA0.f.x + accA0.f.y, 0.f);
        float nA1 = fmaxf(accA1.f.x + accA1.f.y, 0.f);
        float nB0 = fmaxf(accB0.f.x + accB0.f.y, 0.f);
        float nB1 = fmaxf(accB1.f.x + accB1.f.y, 0.f);
        P2 hdA0 = dup2(nA0), hdA1 = dup2(nA1);
        P2 hdB0 = dup2(nB0), hdB1 = dup2(nB1);

        // L3 scatter: contribution of h2[2ch], h2[2ch+1] into all 16 outputs
#pragma unroll
        for (int qq = 0; qq < 8; qq++) {
            const float4* w3p = reinterpret_cast<const float4*>(cD.W3 + qq * 32 + ch * 2);
            float4 w = w3p[0];
            P2 wa = mk2(w.x, w.y), wb = mk2(w.z, w.w);
            oA[qq] = fma2(wa, hdA0, oA[qq]);
            oB[qq] = fma2(wa, hdB0, oB[qq]);
            oA[qq] = fma2(wb, hdA1, oA[qq]);
            oB[qq] = fma2(wb, hdB1, oB[qq]);
        }
    }

    // ---- stores: oX[q] = (neuron 2q, neuron 2q+1) ----
    float4* op0 = reinterpret_cast<float4*>(out + (size_t)r0 * 16);
#pragma unroll
    for (int q = 0; q < 4; q++)
        op0[q] = make_float4(oA[2 * q].f.x, oA[2 * q].f.y, oA[2 * q + 1].f.x, oA[2 * q + 1].f.y);
    if (has1) {
        float4* op1 = reinterpret_cast<float4*>(out + (size_t)r1 * 16);
#pragma unroll
        for (int q = 0; q < 4; q++)
            op1[q] = make_float4(oB[2 * q].f.x, oB[2 * q].f.y, oB[2 * q + 1].f.x, oB[2 * q + 1].f.y);
    }
}

extern "C" void kernel_launch(void* const* d_in, const int* in_sizes, int n_in,
                              void* d_out, int out_size) {
    const float* x  = (const float*)d_in[0];
    const float* qw = (const float*)d_in[1];
    const float* W1 = (const float*)d_in[2];
    const float* b1 = (const float*)d_in[3];
    const float* W2 = (const float*)d_in[4];
    const float* b2 = (const float*)d_in[5];
    const float* W3 = (const float*)d_in[6];
    const float* b3 = (const float*)d_in[7];
    float* out = (float*)d_out;

    int nrows = in_sizes[0] / 16;

    // 1) rearrange weights + compute coefficients into device staging
    qae_prep<<<1, 256>>>(qw, W1, b1, W2, b2, W3, b3);

    // 2) copy staging into the constant bank (D2D, graph-capturable, alloc-free)
    void* stage_ptr = nullptr;
    cudaGetSymbolAddress(&stage_ptr, gStage);
    cudaMemcpyToSymbolAsync(cD, stage_ptr, sizeof(CData), 0, cudaMemcpyDeviceToDevice, 0);

    // 3) main kernel
    int grid = (nrows + NT * 2 - 1) / (NT * 2);
    qae15_kernel<<<grid, NT>>>(x, out, nrows);
}

// round 16
// speedup vs baseline: 1.3765x; 1.0006x over previous
#include <cuda_runtime.h>

#define NT 128
#define PI_F 3.14159265358979323846f

struct __align__(16) CData {
    float2 W1[32];    // neuron-pair interleaved: idx i -> p=i>>2,k=i&3 : (W1[2p][k], W1[2p+1][k])
    float  W2[512];   // plain row-major [32][16]
    float2 W3[256];   // pair-interleaved [8 pairs][32 k]
    float2 b1[8];
    float  b2[32];
    float2 b3[8];
    float2 K[30];     // Pauli coefficients, duplicated lanes
};

__constant__ CData cD;

// ---------- packed f32x2 primitives ----------
struct P2 { union { float2 f; unsigned long long u; }; };

__device__ __forceinline__ P2 mk2(float a, float b) { P2 p; p.f.x = a; p.f.y = b; return p; }
__device__ __forceinline__ P2 dup2(float a) { return mk2(a, a); }

__device__ __forceinline__ P2 fma2(P2 a, P2 b, P2 c) {
    P2 d;
    asm("fma.rn.f32x2 %0, %1, %2, %3;" : "=l"(d.u) : "l"(a.u), "l"(b.u), "l"(c.u));
    return d;
}
__device__ __forceinline__ P2 mul2(P2 a, P2 b) {
    P2 d;
    asm("mul.rn.f32x2 %0, %1, %2;" : "=l"(d.u) : "l"(a.u), "l"(b.u));
    return d;
}
__device__ __forceinline__ P2 relu2(P2 a) {
    P2 d; d.f.x = fmaxf(a.f.x, 0.f); d.f.y = fmaxf(a.f.y, 0.f); return d;
}

// ---------- prep kernel: rearrange weights + coefficients DIRECTLY into cD's backing store ----------
__global__ void qae_prep(CData* __restrict__ dst,
                         const float* __restrict__ qw,
                         const float* __restrict__ W1, const float* __restrict__ b1,
                         const float* __restrict__ W2, const float* __restrict__ b2,
                         const float* __restrict__ W3, const float* __restrict__ b3)
{
    const int tid = threadIdx.x;
    for (int i = tid; i < 32; i += 256) {
        int p = i >> 2, k = i & 3;
        dst->W1[i] = make_float2(W1[(2 * p) * 4 + k], W1[(2 * p + 1) * 4 + k]);
    }
    for (int i = tid; i < 512; i += 256)
        dst->W2[i] = W2[i];
    for (int i = tid; i < 256; i += 256) {
        int p3 = i >> 5, k3 = i & 31;
        dst->W3[i] = make_float2(W3[(2 * p3) * 32 + k3], W3[(2 * p3 + 1) * 32 + k3]);
    }
    if (tid < 8)  dst->b1[tid] = make_float2(b1[2 * tid], b1[2 * tid + 1]);
    if (tid < 32) dst->b2[tid] = b2[tid];
    if (tid < 8)  dst->b3[tid] = make_float2(b3[2 * tid], b3[2 * tid + 1]);
    if (tid == 0) {
        float c[4], s[4];
#pragma unroll
        for (int i = 0; i < 4; i++) __sincosf(qw[2 * i], &s[i], &c[i]);
        float kv[30];
        kv[0]  =  c[0];                    kv[1]  = -s[0];
        kv[2]  =  c[0] * c[1];             kv[3]  = -c[0] * s[1];
        kv[4]  =  s[0] * c[1];             kv[5]  =  s[0] * s[1];
        kv[6]  =  c[0] * c[1] * c[2];      kv[7]  = -c[0] * c[1] * s[2];
        kv[8]  =  c[0] * s[1] * c[2];      kv[9]  =  c[0] * s[1] * s[2];
        kv[10] = -s[0] * c[1] * c[2];      kv[11] = -s[0] * c[1] * s[2];
        kv[12] = -s[0] * s[1] * c[2];      kv[13] = -s[0] * s[1] * s[2];
        kv[14] =  c[0] * c[1] * c[2] * c[3];
        kv[15] =  s[0] * c[1] * c[2] * c[3];
        kv[16] = -c[0] * s[1] * c[2] * c[3];
        kv[17] =  c[0] * c[1] * s[2] * c[3];
        kv[18] = -c[0] * c[1] * c[2] * s[3];
        kv[19] =  s[0] * s[1] * c[2] * c[3];
        kv[20] = -s[0] * c[1] * s[2] * c[3];
        kv[21] =  s[0] * c[1] * c[2] * s[3];
        kv[22] = -c[0] * s[1] * s[2] * c[3];
        kv[23] = -c[0] * s[1] * c[2] * s[3];
        kv[24] =  c[0] * c[1] * s[2] * s[3];
        kv[25] =  s[0] * s[1] * s[2] * c[3];
        kv[26] =  s[0] * s[1] * c[2] * s[3];
        kv[27] =  s[0] * c[1] * s[2] * s[3];
        kv[28] = -c[0] * s[1] * s[2] * s[3];
        kv[29] =  s[0] * s[1] * s[2] * s[3];
#pragma unroll
        for (int i = 0; i < 30; i++) dst->K[i] = make_float2(kv[i], kv[i]);
    }
}

// Bloch-sphere / Pauli-string collapsed quantum encoder for one lane-packed row pair.
__device__ __forceinline__ void compute_zv(const float xsA[8], const float xsB[8], P2 zv[4])
{
    P2 X[4], Y[4], Z[4];
#pragma unroll
    for (int i = 0; i < 4; i++) {
        float saA, caA, sbA, cbA, saB, caB, sbB, cbB;
        __sincosf(xsA[i]     * PI_F, &saA, &caA);
        __sincosf(xsA[i + 4] * PI_F, &sbA, &cbA);
        __sincosf(xsB[i]     * PI_F, &saB, &caB);
        __sincosf(xsB[i + 4] * PI_F, &sbB, &cbB);
        P2 sa = mk2(saA, saB), sb = mk2(sbA, sbB), cb = mk2(cbA, cbB);
        X[i] = mul2(sa, cb);
        Y[i] = mul2(sa, sb);
        Z[i] = mk2(caA, caB);
    }

    P2 A  = mul2(X[0], X[1]);
    P2 B  = mul2(Y[0], Y[1]);
    P2 F  = mul2(X[1], X[2]);
    P2 H  = mul2(X[0], X[2]);
    P2 D  = mul2(X[2], X[3]);
    P2 E  = mul2(Y[2], Y[3]);
    P2 G  = mul2(Y[1], Y[2]);
    P2 ZF = mul2(Z[0], F);
    P2 Z0Z2 = mul2(Z[0], Z[2]);
    P2 YZ   = mul2(Y[0], Z[1]);
    P2 YZY  = mul2(YZ, Y[2]);

#define KLD(n) ({ P2 _k; _k.f = cD.K[n]; _k; })

    P2 z0 = mul2(KLD(0), Z[0]);
    z0 = fma2(KLD(1), A, z0);

    P2 z1 = mul2(KLD(2), Z[1]);
    z1 = fma2(KLD(3), ZF, z1);
    z1 = fma2(KLD(4), B, z1);
    z1 = fma2(KLD(5), H, z1);

    P2 Z1D   = mul2(Z[1], D);
    P2 X1X3  = mul2(X[1], X[3]);
    P2 ZX1X3 = mul2(Z[0], X1X3);
    P2 AZ2   = mul2(A, Z[2]);
    P2 BD    = mul2(B, D);
    P2 X0X3  = mul2(X[0], X[3]);
    P2 z2 = mul2(KLD(6), Z0Z2);
    z2 = fma2(KLD(7),  Z1D,   z2);
    z2 = fma2(KLD(8),  G,     z2);
    z2 = fma2(KLD(9),  ZX1X3, z2);
    z2 = fma2(KLD(10), AZ2,   z2);
    z2 = fma2(KLD(11), BD,    z2);
    z2 = fma2(KLD(12), YZY,   z2);
    z2 = fma2(KLD(13), X0X3,  z2);

    P2 Z1Z3 = mul2(Z[1], Z[3]);
    P2 BZ3  = mul2(B, Z[3]);
    P2 ZF3  = mul2(ZF, Z[3]);
    P2 Z0E  = mul2(Z[0], E);
    P2 ZZX  = mul2(Z0Z2, X[3]);
    P2 HZ3  = mul2(H, Z[3]);
    P2 AE   = mul2(A, E);
    P2 AZX  = mul2(AZ2, X[3]);
    P2 Y1Z2 = mul2(Y[1], Z[2]);
    P2 YZ2Y3 = mul2(Y1Z2, Y[3]);
    P2 GX3  = mul2(G, X[3]);
    P2 Z1X2 = mul2(Z[1], X[2]);
    P2 YZZ  = mul2(YZ, Z[2]);
    P2 YZZY = mul2(YZZ, Y[3]);
    P2 YZYX = mul2(YZY, X[3]);
    P2 BX2  = mul2(B, X[2]);
    P2 Z0X1 = mul2(Z[0], X[1]);
    P2 z3 = mul2(KLD(14), Z1Z3);
    z3 = fma2(KLD(15), BZ3,   z3);
    z3 = fma2(KLD(16), ZF3,   z3);
    z3 = fma2(KLD(17), Z0E,   z3);
    z3 = fma2(KLD(18), ZZX,   z3);
    z3 = fma2(KLD(19), HZ3,   z3);
    z3 = fma2(KLD(20), AE,    z3);
    z3 = fma2(KLD(21), AZX,   z3);
    z3 = fma2(KLD(22), YZ2Y3, z3);
    z3 = fma2(KLD(23), GX3,   z3);
    z3 = fma2(KLD(24), Z1X2,  z3);
    z3 = fma2(KLD(25), YZZY,  z3);
    z3 = fma2(KLD(26), YZYX,  z3);
    z3 = fma2(KLD(27), BX2,   z3);
    z3 = fma2(KLD(28), Z0X1,  z3);
    z3 = fma2(KLD(29), X[0],  z3);

    zv[0] = z0; zv[1] = z1; zv[2] = z2; zv[3] = z3;
}

__global__ void __launch_bounds__(NT, 6)
qae16_kernel(const float* __restrict__ x, float* __restrict__ out, int nrows)
{
    const int tid = threadIdx.x;
    const int r0 = blockIdx.x * (NT * 2) + tid;
    const int r1 = r0 + NT;
    if (r0 >= nrows) return;
    const bool has1 = (r1 < nrows);
    const int r1c = has1 ? r1 : r0;

    // ---- load features ----
    const float4* xp0 = reinterpret_cast<const float4*>(x + (size_t)r0 * 16);
    const float4* xp1 = reinterpret_cast<const float4*>(x + (size_t)r1c * 16);
    float4 a0 = xp0[0], a1 = xp0[1];
    float4 c0 = xp1[0], c1 = xp1[1];
    float xsA[8] = {a0.x, a0.y, a0.z, a0.w, a1.x, a1.y, a1.z, a1.w};
    float xsB[8] = {c0.x, c0.y, c0.z, c0.w, c1.x, c1.y, c1.z, c1.w};

    // ---- quantum encoder (lane-packed row pair) ----
    P2 zv[4];
    compute_zv(xsA, xsB, zv);

    P2 zdA[4], zdB[4];
#pragma unroll
    for (int k = 0; k < 4; k++) { zdA[k] = dup2(zv[k].f.x); zdB[k] = dup2(zv[k].f.y); }

    // ---- Layer 1: 4 -> 16 ; h1 stored as neuron pairs (h1[2p], h1[2p+1]) ----
    P2 h1A[8], h1B[8];
#pragma unroll
    for (int pp = 0; pp < 8; pp++) {
        const float4* wp = reinterpret_cast<const float4*>(cD.W1 + pp * 4);
        float4 w0 = wp[0], w1 = wp[1];
        P2 wk0 = mk2(w0.x, w0.y), wk1 = mk2(w0.z, w0.w);
        P2 wk2 = mk2(w1.x, w1.y), wk3 = mk2(w1.z, w1.w);
        P2 accA; accA.f = cD.b1[pp];
        P2 accB = accA;
        accA = fma2(wk0, zdA[0], accA); accB = fma2(wk0, zdB[0], accB);
        accA = fma2(wk1, zdA[1], accA); accB = fma2(wk1, zdB[1], accB);
        accA = fma2(wk2, zdA[2], accA); accB = fma2(wk2, zdB[2], accB);
        accA = fma2(wk3, zdA[3], accA); accB = fma2(wk3, zdB[3], accB);
        h1A[pp] = relu2(accA); h1B[pp] = relu2(accB);
    }

    // ---- Fused Layers 2+3: h2 never materializes ----
    P2 oA[8], oB[8];
#pragma unroll
    for (int qq = 0; qq < 8; qq++) { oA[qq].f = cD.b3[qq]; oB[qq] = oA[qq]; }

#pragma unroll
    for (int ch = 0; ch < 16; ch++) {
        // L2: h2 neurons 2ch, 2ch+1 via packed dot products (bias seeds lane x)
        const float4* w2r0 = reinterpret_cast<const float4*>(cD.W2 + (2 * ch) * 16);
        const float4* w2r1 = reinterpret_cast<const float4*>(cD.W2 + (2 * ch + 1) * 16);
        P2 accA0 = mk2(cD.b2[2 * ch], 0.f);
        P2 accA1 = mk2(cD.b2[2 * ch + 1], 0.f);
        P2 accB0 = accA0, accB1 = accA1;
#pragma unroll
        for (int j4 = 0; j4 < 4; j4++) {
            float4 w0 = w2r0[j4];
            float4 w1 = w2r1[j4];
            P2 w0a = mk2(w0.x, w0.y), w0b = mk2(w0.z, w0.w);
            P2 w1a = mk2(w1.x, w1.y), w1b = mk2(w1.z, w1.w);
            P2 hA0 = h1A[2 * j4], hA1 = h1A[2 * j4 + 1];
            P2 hB0 = h1B[2 * j4], hB1 = h1B[2 * j4 + 1];
            accA0 = fma2(w0a, hA0, accA0); accA0 = fma2(w0b, hA1, accA0);
            accA1 = fma2(w1a, hA0, accA1); accA1 = fma2(w1b, hA1, accA1);
            accB0 = fma2(w0a, hB0, accB0); accB0 = fma2(w0b, hB1, accB0);
            accB1 = fma2(w1a, hB0, accB1); accB1 = fma2(w1b, hB1, accB1);
        }
        float nA0 = fmaxf(accA0.f.x + accA0.f.y, 0.f);
        float nA1 = fmaxf(accA1.f.x + accA1.f.y, 0.f);
        float nB0 = fmaxf(accB0.f.x + accB0.f.y, 0.f);
        float nB1 = fmaxf(accB1.f.x + accB1.f.y, 0.f);
        P2 hdA0 = dup2(nA0), hdA1 = dup2(nA1);
        P2 hdB0 = dup2(nB0), hdB1 = dup2(nB1);

        // L3 scatter: contribution of h2[2ch], h2[2ch+1] into all 16 outputs
#pragma unroll
        for (int qq = 0; qq < 8; qq++) {
            const float4* w3p = reinterpret_cast<const float4*>(cD.W3 + qq * 32 + ch * 2);
            float4 w = w3p[0];
            P2 wa = mk2(w.x, w.y), wb = mk2(w.z, w.w);
            oA[qq] = fma2(wa, hdA0, oA[qq]);
            oB[qq] = fma2(wa, hdB0, oB[qq]);
            oA[qq] = fma2(wb, hdA1, oA[qq]);
            oB[qq] = fma2(wb, hdB1, oB[qq]);
        }
    }

    // ---- stores: oX[q] = (neuron 2q, neuron 2q+1) ----
    float4* op0 = reinterpret_cast<float4*>(out + (size_t)r0 * 16);
#pragma unroll
    for (int q = 0; q < 4; q++)
        op0[q] = make_float4(oA[2 * q].f.x, oA[2 * q].f.y, oA[2 * q + 1].f.x, oA[2 * q + 1].f.y);
    if (has1) {
        float4* op1 = reinterpret_cast<float4*>(out + (size_t)r1 * 16);
#pragma unroll
        for (int q = 0; q < 4; q++)
            op1[q] = make_float4(oB[2 * q].f.x, oB[2 * q].f.y, oB[2 * q + 1].f.x, oB[2 * q + 1].f.y);
    }
}

extern "C" void kernel_launch(void* const* d_in, const int* in_sizes, int n_in,
                              void* d_out, int out_size) {
    const float* x  = (const float*)d_in[0];
    const float* qw = (const float*)d_in[1];
    const float* W1 = (const float*)d_in[2];
    const float* b1 = (const float*)d_in[3];
    const float* W2 = (const float*)d_in[4];
    const float* b2 = (const float*)d_in[5];
    const float* W3 = (const float*)d_in[6];
    const float* b3 = (const float*)d_in[7];
    float* out = (float*)d_out;

    int nrows = in_sizes[0] / 16;

    // prep kernel writes the rearranged weights + coefficients DIRECTLY into
    // cD's backing store (same memory the D2D memcpyToSymbol would target).
    // Constant cache is invalidated at kernel-launch boundaries, so qae16_kernel
    // observes the fresh values. One graph node instead of two.
    void* cptr = nullptr;
    cudaGetSymbolAddress(&cptr, cD);   // pure query; capture-safe
    qae_prep<<<1, 256>>>((CData*)cptr, qw, W1, b1, W2, b2, W3, b3);

    int grid = (nrows + NT * 2 - 1) / (NT * 2);
    qae16_kernel<<<grid, NT>>>(x, out, nrows);
}